// round 1
// baseline (speedup 1.0000x reference)
#include <cuda_runtime.h>
#include <cuda_bf16.h>

// ---------------------------------------------------------------------------
// QuantumHybridQLSTM — closed-form quantum gate + split GEMM/recurrence.
//
// Quantum circuit identity (Heisenberg picture through the CNOT chain):
//   expz[w] = cos(phi_w) * prod_{j<=w} cos(theta_j)     (w = 0..6)
//   expz[7] = cos(theta_7 + phi_7) * prod_{j<=6} cos(theta_j)
//
// theta = [x_t, h] @ W^T + b splits into:
//   Zx[t,b,g,k] = b_g[k] + sum_d x[t,b,d] * W_g[k,d]    (precomputed GEMM)
//   theta       = Zx + Wh_g[k,:] . h                    (recurrent, 8x8)
// ---------------------------------------------------------------------------

#define SEQ 64
#define BATCH 256
#define IN_DIM 64
#define NOUT 32   // 4 gates * 8 outputs

// scratch: Zx, padded by one extra timestep so the prefetch never reads OOB
__device__ float g_zx[(SEQ + 1) * BATCH * NOUT];

__device__ __forceinline__ float fsigmoid(float x) {
    float e = __expf(-x);
    return __fdividef(1.0f, 1.0f + e);
}
__device__ __forceinline__ float ftanh(float x) {
    float a = fabsf(x);
    float e = __expf(-2.0f * a);
    float t = (1.0f - e) * __fdividef(1.0f, 1.0f + e);
    return copysignf(t, x);
}

// ---------------------------------------------------------------------------
// Kernel 1: Zx[t*256+b][g*8+k] = b_g[k] + sum_{d<64} x[(t*256+b)*64+d]*W_g[k*72+d]
// grid 128 x 128 threads, one row per thread.
// ---------------------------------------------------------------------------
__global__ __launch_bounds__(128, 1) void qlstm_gemm_kernel(
    const float* __restrict__ inputs,
    const float* __restrict__ Wf, const float* __restrict__ bf,
    const float* __restrict__ Wi, const float* __restrict__ bi,
    const float* __restrict__ Wg, const float* __restrict__ bg,
    const float* __restrict__ Wo, const float* __restrict__ bo)
{
    __shared__ float ws[NOUT * IN_DIM];   // [g*8+k][d]
    __shared__ float bs[NOUT];

    const int tid = threadIdx.x;

    // cooperative load of the 4 gate weight blocks (first 64 cols of each 8x72)
    {
        const float* W;
        #pragma unroll
        for (int g = 0; g < 4; g++) {
            W = (g == 0) ? Wf : (g == 1) ? Wi : (g == 2) ? Wg : Wo;
            for (int i = tid; i < 8 * IN_DIM; i += 128) {
                int k = i >> 6, d = i & 63;
                ws[g * 8 * IN_DIM + i] = W[k * 72 + d];
            }
        }
        if (tid < NOUT) {
            const float* bp = (tid < 8) ? bf : (tid < 16) ? bi : (tid < 24) ? bg : bo;
            bs[tid] = bp[tid & 7];
        }
    }
    __syncthreads();

    const int r = blockIdx.x * 128 + tid;   // 0 .. 16383  (t*256+b)

    float4 x4[16];
    const float4* xp = (const float4*)(inputs + (size_t)r * IN_DIM);
    #pragma unroll
    for (int i = 0; i < 16; i++) x4[i] = xp[i];

    float out[NOUT];
    #pragma unroll
    for (int o = 0; o < NOUT; o++) {
        float acc = bs[o];
        const float4* w4 = (const float4*)(ws + o * IN_DIM);
        #pragma unroll
        for (int i = 0; i < 16; i++) {
            float4 w = w4[i];
            acc = fmaf(x4[i].x, w.x, acc);
            acc = fmaf(x4[i].y, w.y, acc);
            acc = fmaf(x4[i].z, w.z, acc);
            acc = fmaf(x4[i].w, w.w, acc);
        }
        out[o] = acc;
    }

    float4* zp = (float4*)(g_zx + (size_t)r * NOUT);
    #pragma unroll
    for (int i = 0; i < 8; i++)
        zp[i] = make_float4(out[4 * i], out[4 * i + 1], out[4 * i + 2], out[4 * i + 3]);
}

// ---------------------------------------------------------------------------
// Kernel 2: recurrence. 64 blocks x 32 threads.
// lane = (b_local<<3) | k : 4 batch elements per warp, 8 output lanes each.
// ---------------------------------------------------------------------------
__global__ __launch_bounds__(32, 1) void qlstm_rec_kernel(
    const float* __restrict__ Wf, const float* __restrict__ qf,
    const float* __restrict__ Wi, const float* __restrict__ qi,
    const float* __restrict__ Wg, const float* __restrict__ qg,
    const float* __restrict__ Wo, const float* __restrict__ qo,
    float* __restrict__ out)
{
    const int lane = threadIdx.x;
    const int k = lane & 7;
    const int b = blockIdx.x * 4 + (lane >> 3);

    // recurrent weights Wh_g[k][j] = W_g[k*72 + 64 + j], plus qparam folding:
    //   k<7 : multiply prefix by cos(phi_k);  k==7 : add phi_7 into theta_7.
    float wh[4][8], cphi[4], addq[4];
    {
        const float* Wp[4] = {Wf, Wi, Wg, Wo};
        const float* qp[4] = {qf, qi, qg, qo};
        #pragma unroll
        for (int g = 0; g < 4; g++) {
            #pragma unroll
            for (int j = 0; j < 8; j++) wh[g][j] = Wp[g][k * 72 + 64 + j];
            float q = qp[g][k];
            if (k == 7) { cphi[g] = 1.0f;      addq[g] = q;    }
            else        { cphi[g] = __cosf(q); addq[g] = 0.0f; }
        }
    }

    float h = 0.0f, c = 0.0f;

    // preload step 0
    const float* zb = g_zx + (size_t)b * NOUT + k;
    float z0 = zb[0], z1 = zb[8], z2 = zb[16], z3 = zb[24];

    for (int t = 0; t < SEQ; t++) {
        // prefetch next timestep (padded array -> safe at t=63)
        const float* zn = g_zx + ((size_t)(t + 1) * BATCH + b) * NOUT + k;
        float n0 = zn[0], n1 = zn[8], n2 = zn[16], n3 = zn[24];

        // theta_g = Zx + Wh . h   (h broadcast across the 8-lane segment)
        float th0 = z0, th1 = z1, th2 = z2, th3 = z3;
        #pragma unroll
        for (int j = 0; j < 8; j++) {
            float hj = __shfl_sync(0xffffffffu, h, j, 8);
            th0 = fmaf(wh[0][j], hj, th0);
            th1 = fmaf(wh[1][j], hj, th1);
            th2 = fmaf(wh[2][j], hj, th2);
            th3 = fmaf(wh[3][j], hj, th3);
        }

        float v0 = __cosf(th0 + addq[0]);
        float v1 = __cosf(th1 + addq[1]);
        float v2 = __cosf(th2 + addq[2]);
        float v3 = __cosf(th3 + addq[3]);

        // inclusive prefix product over the 8-lane segment (3 shfl rounds)
        #pragma unroll
        for (int off = 1; off < 8; off <<= 1) {
            float u0 = __shfl_up_sync(0xffffffffu, v0, off, 8);
            float u1 = __shfl_up_sync(0xffffffffu, v1, off, 8);
            float u2 = __shfl_up_sync(0xffffffffu, v2, off, 8);
            float u3 = __shfl_up_sync(0xffffffffu, v3, off, 8);
            if (k >= off) { v0 *= u0; v1 *= u1; v2 *= u2; v3 *= u3; }
        }

        float ef = cphi[0] * v0;
        float ei = cphi[1] * v1;
        float eg = cphi[2] * v2;
        float eo = cphi[3] * v3;

        float f  = fsigmoid(ef);
        float ii = fsigmoid(ei);
        float gg = ftanh(eg);
        float o  = fsigmoid(eo);

        c = fmaf(f, c, ii * gg);
        h = o * ftanh(c);

        out[((size_t)t * BATCH + b) * 8 + k] = h;

        z0 = n0; z1 = n1; z2 = n2; z3 = n3;
    }

    // trailing (hx, cx) — flattened after outputs
    const size_t base = (size_t)SEQ * BATCH * 8;
    out[base + (size_t)b * 8 + k] = h;
    out[base + (size_t)BATCH * 8 + (size_t)b * 8 + k] = c;
}

extern "C" void kernel_launch(void* const* d_in, const int* in_sizes, int n_in,
                              void* d_out, int out_size) {
    const float* inputs = (const float*)d_in[0];
    const float* Wf = (const float*)d_in[1];
    const float* bf = (const float*)d_in[2];
    const float* qf = (const float*)d_in[3];
    const float* Wi = (const float*)d_in[4];
    const float* bi = (const float*)d_in[5];
    const float* qi = (const float*)d_in[6];
    const float* Wg = (const float*)d_in[7];
    const float* bg = (const float*)d_in[8];
    const float* qg = (const float*)d_in[9];
    const float* Wo = (const float*)d_in[10];
    const float* bo = (const float*)d_in[11];
    const float* qo = (const float*)d_in[12];
    float* out = (float*)d_out;

    qlstm_gemm_kernel<<<128, 128>>>(inputs, Wf, bf, Wi, bi, Wg, bg, Wo, bo);
    qlstm_rec_kernel<<<64, 32>>>(Wf, qf, Wi, qi, Wg, qg, Wo, qo, out);
}

// round 2
// speedup vs baseline: 1.0656x; 1.0656x over previous
#include <cuda_runtime.h>
#include <cuda_bf16.h>

// ---------------------------------------------------------------------------
// QuantumHybridQLSTM — closed-form quantum gate + split GEMM/recurrence.
//
// Quantum circuit identity (Heisenberg picture through the CNOT chain):
//   expz[w] = cos(phi_w) * prod_{j<=w} cos(theta_j)     (w = 0..6)
//   expz[7] = cos(theta_7 + phi_7) * prod_{j<=6} cos(theta_j)
//
// theta = [x_t, h] @ W^T + b splits into:
//   Zx[t,b,g,k] = b_g[k] + sum_d x[t,b,d] * W_g[k,d]    (precomputed GEMM)
//   theta       = Zx + Wh_g[k,:] . h                    (recurrent, 8x8)
//
// R1: recurrence uses 1 warp per batch element, lane = (gate, k).
//     Parallel-shuffle prefix product, unified activation, approx ex2/rcp.
// ---------------------------------------------------------------------------

#define SEQ 64
#define BATCH 256
#define IN_DIM 64
#define NOUT 32   // 4 gates * 8 outputs

// scratch: Zx, padded by one extra timestep so the prefetch never reads OOB
__device__ float g_zx[(SEQ + 1) * BATCH * NOUT];

__device__ __forceinline__ float fex2(float x) {
    float y; asm("ex2.approx.ftz.f32 %0, %1;" : "=f"(y) : "f"(x)); return y;
}
__device__ __forceinline__ float frcp(float x) {
    float y; asm("rcp.approx.ftz.f32 %0, %1;" : "=f"(y) : "f"(x)); return y;
}

// ---------------------------------------------------------------------------
// Kernel 1: Zx[t*256+b][g*8+k] = b_g[k] + sum_{d<64} x[(t*256+b)*64+d]*W_g[k*72+d]
// grid 128 x 128 threads, one row per thread.
// ---------------------------------------------------------------------------
__global__ __launch_bounds__(128, 1) void qlstm_gemm_kernel(
    const float* __restrict__ inputs,
    const float* __restrict__ Wf, const float* __restrict__ bf,
    const float* __restrict__ Wi, const float* __restrict__ bi,
    const float* __restrict__ Wg, const float* __restrict__ bg,
    const float* __restrict__ Wo, const float* __restrict__ bo)
{
    __shared__ float ws[NOUT * IN_DIM];   // [g*8+k][d]
    __shared__ float bs[NOUT];

    const int tid = threadIdx.x;

    {
        const float* W;
        #pragma unroll
        for (int g = 0; g < 4; g++) {
            W = (g == 0) ? Wf : (g == 1) ? Wi : (g == 2) ? Wg : Wo;
            for (int i = tid; i < 8 * IN_DIM; i += 128) {
                int k = i >> 6, d = i & 63;
                ws[g * 8 * IN_DIM + i] = W[k * 72 + d];
            }
        }
        if (tid < NOUT) {
            const float* bp = (tid < 8) ? bf : (tid < 16) ? bi : (tid < 24) ? bg : bo;
            bs[tid] = bp[tid & 7];
        }
    }
    __syncthreads();

    const int r = blockIdx.x * 128 + tid;   // 0 .. 16383  (t*256+b)

    float4 x4[16];
    const float4* xp = (const float4*)(inputs + (size_t)r * IN_DIM);
    #pragma unroll
    for (int i = 0; i < 16; i++) x4[i] = xp[i];

    float out[NOUT];
    #pragma unroll
    for (int o = 0; o < NOUT; o++) {
        float acc = bs[o];
        const float4* w4 = (const float4*)(ws + o * IN_DIM);
        #pragma unroll
        for (int i = 0; i < 16; i++) {
            float4 w = w4[i];
            acc = fmaf(x4[i].x, w.x, acc);
            acc = fmaf(x4[i].y, w.y, acc);
            acc = fmaf(x4[i].z, w.z, acc);
            acc = fmaf(x4[i].w, w.w, acc);
        }
        out[o] = acc;
    }

    float4* zp = (float4*)(g_zx + (size_t)r * NOUT);
    #pragma unroll
    for (int i = 0; i < 8; i++)
        zp[i] = make_float4(out[4 * i], out[4 * i + 1], out[4 * i + 2], out[4 * i + 3]);
}

// ---------------------------------------------------------------------------
// Kernel 2: recurrence. 256 blocks x 32 threads. One warp per batch element.
// lane = g*8 + k  (g = gate 0..3 [f,i,g,o], k = output index 0..7)
// ---------------------------------------------------------------------------
__global__ __launch_bounds__(32, 1) void qlstm_rec_kernel(
    const float* __restrict__ Wf, const float* __restrict__ qf,
    const float* __restrict__ Wi, const float* __restrict__ qi,
    const float* __restrict__ Wg, const float* __restrict__ qg,
    const float* __restrict__ Wo, const float* __restrict__ qo,
    float* __restrict__ out)
{
    const int lane = threadIdx.x;
    const int g = lane >> 3;
    const int k = lane & 7;
    const int b = blockIdx.x;
    const unsigned FULL = 0xffffffffu;

    const float* W = (g == 0) ? Wf : (g == 1) ? Wi : (g == 2) ? Wg : Wo;
    const float* q = (g == 0) ? qf : (g == 1) ? qi : (g == 2) ? qg : qo;

    // recurrent weights: W[k*72 + 64 + j]
    float wh[8];
    #pragma unroll
    for (int j = 0; j < 8; j++) wh[j] = W[k * 72 + 64 + j];

    const float qv = q[k];
    const float addq = (k == 7) ? qv : 0.0f;       // fold phi_7 into theta_7
    const float cphi = (k == 7) ? 1.0f : __cosf(qv);

    // unified activation: act(x) = A * rcp(1 + ex2(M*x)) + Badd
    //   sigmoid (g=0,1,3): A=1, M=-log2e, Badd=0
    //   tanh    (g=2):     A=2, M=-2log2e, Badd=-1
    const float L2E = 1.4426950408889634f;
    const float actA = (g == 2) ? 2.0f : 1.0f;
    const float actM = (g == 2) ? (-2.0f * L2E) : (-L2E);
    const float actB = (g == 2) ? -1.0f : 0.0f;
    const float TM = -2.0f * L2E;   // for tanh(c)

    float h = 0.0f, c = 0.0f;

    const float* zp = g_zx + (size_t)b * NOUT + lane;
    float z = zp[0];   // step 0

    float* outp = out + (size_t)b * 8 + k;
    const size_t tail = (size_t)SEQ * BATCH * 8;

    for (int t = 0; t < SEQ; t++) {
        // prefetch next timestep (padded array -> safe at t=63)
        float zn = zp[(size_t)(t + 1) * (BATCH * NOUT)];

        // theta = z + addq + Wh . h   (h_k lives in lane k of every 8-group)
        float acc0 = z, acc1 = addq;
        #pragma unroll
        for (int j = 0; j < 8; j += 2) {
            float ha = __shfl_sync(FULL, h, j, 8);
            float hb = __shfl_sync(FULL, h, j + 1, 8);
            acc0 = fmaf(wh[j], ha, acc0);
            acc1 = fmaf(wh[j + 1], hb, acc1);
        }
        float v = __cosf(acc0 + acc1);

        // prefix product over the 8-lane segment: one parallel shuffle round
        // + select + tree multiply  (pp[j] = j<=k ? v_j : 1)
        float pp[8];
        #pragma unroll
        for (int j = 0; j < 8; j++) {
            float vj = __shfl_sync(FULL, v, j, 8);
            pp[j] = (j <= k) ? vj : 1.0f;
        }
        pp[0] *= pp[1]; pp[2] *= pp[3]; pp[4] *= pp[5]; pp[6] *= pp[7];
        pp[0] *= pp[2]; pp[4] *= pp[6];
        float ez = cphi * (pp[0] * pp[4]);

        // activation (per-lane gate type)
        float a = fmaf(actA, frcp(1.0f + fex2(actM * ez)), actB);

        // gather the 4 gate values for this k (parallel shuffle round)
        float af = __shfl_sync(FULL, a, k, 32);
        float ai = __shfl_sync(FULL, a, k + 8, 32);
        float ag = __shfl_sync(FULL, a, k + 16, 32);
        float ao = __shfl_sync(FULL, a, k + 24, 32);

        // LSTM update (redundant across the 4 gate groups — keeps h_k in lane k)
        c = fmaf(af, c, ai * ag);
        float tc = fmaf(2.0f, frcp(1.0f + fex2(TM * c)), -1.0f);
        h = ao * tc;

        if (lane < 8) outp[(size_t)t * (BATCH * 8)] = h;

        z = zn;
    }

    // trailing (hx, cx) — flattened after outputs
    if (lane < 8) {
        out[tail + (size_t)b * 8 + k] = h;
        out[tail + (size_t)BATCH * 8 + (size_t)b * 8 + k] = c;
    }
}

extern "C" void kernel_launch(void* const* d_in, const int* in_sizes, int n_in,
                              void* d_out, int out_size) {
    const float* inputs = (const float*)d_in[0];
    const float* Wf = (const float*)d_in[1];
    const float* bf = (const float*)d_in[2];
    const float* qf = (const float*)d_in[3];
    const float* Wi = (const float*)d_in[4];
    const float* bi = (const float*)d_in[5];
    const float* qi = (const float*)d_in[6];
    const float* Wg = (const float*)d_in[7];
    const float* bg = (const float*)d_in[8];
    const float* qg = (const float*)d_in[9];
    const float* Wo = (const float*)d_in[10];
    const float* bo = (const float*)d_in[11];
    const float* qo = (const float*)d_in[12];
    float* out = (float*)d_out;

    qlstm_gemm_kernel<<<128, 128>>>(inputs, Wf, bf, Wi, bi, Wg, bg, Wo, bo);
    qlstm_rec_kernel<<<BATCH, 32>>>(Wf, qf, Wi, qi, Wg, qg, Wo, qo, out);
}